// round 13
// baseline (speedup 1.0000x reference)
#include <cuda_runtime.h>

// LRN (all-ones CxC 5x5 filter), block-specialized overlapped pipeline.
//   chunk = 2 batches (38.5 MB of x, two chunks fit 126 MB L2 together)
//   A(chunk):  s_part[s][b,hw] = sum over 24 channels of x^2   (x -> L2)
//   C(chunk):  per 32x16 tile: f = (2+1e-4*boxsum5x5(sum_s))^-0.75 in smem,
//              then out = x * f  (x from L2 via __ldcs, __stcs streaming out)
// Launch i runs C(i) and A(i+1) IN THE SAME KERNEL via block specialization:
// C blocks [0,196) + A blocks [196,392), 512 threads, one wave -> DRAM reads
// (A) and writes (C) overlap continuously. 9 launches total, no kernel B.
//
// x: [16, 96, 224, 224] fp32.

#define BATCH 16
#define CHAN  96
#define HH    224
#define WW    224
#define HWSZ  (HH * WW)            // 50176
#define CHW   (CHAN * HWSZ)        // 4816896

#define CHUNK_B 2                  // batches per chunk
#define NCHUNK  (BATCH / CHUNK_B)  // 8
#define NSPLIT  4
#define CSPL    (CHAN / NSPLIT)    // 24

#define C_BLOCKS 196               // 2 batches * 14 h-tiles * 7 w-tiles
#define A_BLOCKS 196               // 4 splits * 49 position-blocks
#define NT 512

// Scratch: per-split channel sum of squares (indexed by absolute batch, so
// A(i+1) and C(i) never alias).
__device__ float g_sp[NSPLIT][BATCH * HWSZ];

// ---------------------------------------------------------------------------
// A part: abid in [0,196): split = abid&3, position block = abid>>2 (49 blocks
// of 512 float4-positions cover 2*HWSZ/4 = 25088 exactly).
// ---------------------------------------------------------------------------
__device__ __forceinline__ void a_part(const float* __restrict__ x,
                                       int b0, int abid, int tid) {
    const int s  = abid & 3;
    const int i4 = (abid >> 2) * NT + tid;        // 0..25087
    const int e  = i4 * 4;
    const int lb = e / HWSZ;
    const int hw = e - lb * HWSZ;                 // multiple of 4
    const int b  = b0 + lb;

    const float4* __restrict__ xp = reinterpret_cast<const float4*>(
        x + (size_t)b * CHW + (size_t)(s * CSPL) * HWSZ + hw);

    float4 acc = make_float4(0.f, 0.f, 0.f, 0.f);
#pragma unroll 8
    for (int c = 0; c < CSPL; ++c) {
        float4 v = __ldg(xp + c * (HWSZ / 4));
        acc.x = fmaf(v.x, v.x, acc.x);
        acc.y = fmaf(v.y, v.y, acc.y);
        acc.z = fmaf(v.z, v.z, acc.z);
        acc.w = fmaf(v.w, v.w, acc.w);
    }
    *reinterpret_cast<float4*>(&g_sp[s][(size_t)b * HWSZ + hw]) = acc;
}

// ---------------------------------------------------------------------------
// C part: cbid in [0,196): (b, 16x32 tile). Computes f for the tile in smem
// (separable 5x5 over the summed partials), then out = x * f across channels.
// ---------------------------------------------------------------------------
__device__ __forceinline__ void c_part(const float* __restrict__ x,
                                       float* __restrict__ out,
                                       int b0, int cbid, int tid) {
    __shared__ float sm_s[20 * 36];   // halo sum-of-squares
    __shared__ float sm_t[20 * 32];   // horizontally box-summed
    __shared__ float sm_f[16 * 32];   // final scale factor

    const int b  = b0 + cbid / 98;
    const int r  = cbid % 98;
    const int h0 = (r / 7) * 16;
    const int w0 = (r % 7) * 32;

    // halo: sum the 4 split partials (zero outside image)
    for (int p = tid; p < 20 * 36; p += NT) {
        const int hr = p / 36;
        const int wr = p - hr * 36;
        const int hh = h0 - 2 + hr;
        const int ww = w0 - 2 + wr;
        float v = 0.f;
        if ((unsigned)hh < HH && (unsigned)ww < WW) {
            const size_t off = (size_t)b * HWSZ + hh * WW + ww;
            v = g_sp[0][off] + g_sp[1][off] + g_sp[2][off] + g_sp[3][off];
        }
        sm_s[p] = v;
    }
    __syncthreads();

    // horizontal 5-tap
    for (int p = tid; p < 20 * 32; p += NT) {
        const int rr = p >> 5;
        const int c  = p & 31;
        const float* sr = sm_s + rr * 36 + c;
        sm_t[p] = sr[0] + sr[1] + sr[2] + sr[3] + sr[4];
    }
    __syncthreads();

    // vertical 5-tap + pow
    {
        const int h = tid >> 5;        // 0..15
        const int w = tid & 31;
        float y = sm_t[h * 32 + w] + sm_t[(h + 1) * 32 + w] + sm_t[(h + 2) * 32 + w] +
                  sm_t[(h + 3) * 32 + w] + sm_t[(h + 4) * 32 + w];
        float base = fmaf(1e-4f, y, 2.0f);              // [2, ~3.5): log2/exp2 safe
        sm_f[tid] = exp2f(-0.75f * log2f(base));
    }
    __syncthreads();

    // out = x * f  (float4; 4 channel-groups x 128 float4-pixels)
    const int g  = tid >> 7;            // 0..3
    const int q4 = tid & 127;           // float4 pixel
    const int lh  = q4 >> 3;
    const int lw4 = (q4 & 7) << 2;

    const float4 f4 = reinterpret_cast<const float4*>(sm_f)[q4];
    const size_t base = (size_t)b * CHW + (size_t)(h0 + lh) * WW + (w0 + lw4);

#pragma unroll 4
    for (int c = g; c < CHAN; c += 4) {
        float4 xv = __ldcs(reinterpret_cast<const float4*>(x + base + (size_t)c * HWSZ));
        float4 o;
        o.x = xv.x * f4.x;
        o.y = xv.y * f4.y;
        o.z = xv.z * f4.z;
        o.w = xv.w * f4.w;
        __stcs(reinterpret_cast<float4*>(out + base + (size_t)c * HWSZ), o);
    }
}

// ---------------------------------------------------------------------------
// b0_c < 0: all blocks do A(b0_a).  b0_a < 0: all blocks do C(b0_c).
// Otherwise blocks [0,196) do C(b0_c) (launched first), [196,392) do A(b0_a).
// ---------------------------------------------------------------------------
__global__ void __launch_bounds__(NT) lrn_step_kernel(const float* __restrict__ x,
                                                      float* __restrict__ out,
                                                      int b0_c, int b0_a) {
    const int bid = blockIdx.x;
    const int tid = threadIdx.x;
    if (b0_c < 0)            a_part(x, b0_a, bid, tid);
    else if (b0_a < 0)       c_part(x, out, b0_c, bid, tid);
    else if (bid < C_BLOCKS) c_part(x, out, b0_c, bid, tid);
    else                     a_part(x, b0_a, bid - C_BLOCKS, tid);
}

// ---------------------------------------------------------------------------
extern "C" void kernel_launch(void* const* d_in, const int* in_sizes, int n_in,
                              void* d_out, int out_size) {
    const float* x = (const float*)d_in[0];
    float* out = (float*)d_out;

    // head: fill chunk 0's partial sums
    lrn_step_kernel<<<A_BLOCKS, NT>>>(x, out, -1, 0);
    // steady state: C(i) overlapped with A(i+1)
    for (int i = 0; i + 1 < NCHUNK; ++i)
        lrn_step_kernel<<<C_BLOCKS + A_BLOCKS, NT>>>(x, out, i * CHUNK_B, (i + 1) * CHUNK_B);
    // tail: C of last chunk
    lrn_step_kernel<<<C_BLOCKS, NT>>>(x, out, (NCHUNK - 1) * CHUNK_B, -1);
}